// round 7
// baseline (speedup 1.0000x reference)
#include <cuda_runtime.h>
#include <math.h>

#define H_OUT 32
#define W_OUT 32
#define H_OBJ 8
#define W_OBJ 8
#define HX 128
#define WX 128
#define CH 32
#define BB 32
#define BP 64   // H_OBJ*W_OBJ

// out elements = B*BP*H_OUT*W_OUT*CH
#define OUT_ELEMS (32ll*64*32*32*32)

__device__ __forceinline__ void compute_params(const float* __restrict__ zw,
                                               int b, int i, int j,
                                               float& sx, float& sy, float& tx, float& ty)
{
    const float* z = zw + (((size_t)b * H_OBJ + i) * W_OBJ + j) * 4;
    float z0 = z[0], z1 = z[1], z2 = z[2], z3 = z[3];
    sx = 0.5f / (1.0f + expf(-z0));
    sy = 0.5f / (1.0f + expf(-z1));
    // cr = 0.5 ; i_p = 1.5*i/7 - 0.75 ; j_p = 1.5*j/7 - 0.75
    float bias_tx = 1.5f * (float)j / 7.0f - 0.75f;
    float bias_ty = 1.5f * (float)i / 7.0f - 0.75f;
    tx = 0.5f * tanhf(z2) + bias_tx;
    ty = 0.5f * tanhf(z3) + bias_ty;
}

__global__ void __launch_bounds__(256, 4)
stn_sample_kernel(const float* __restrict__ x,
                  const float* __restrict__ zw,
                  float* __restrict__ out,
                  float* __restrict__ mask)
{
    // blockIdx.x = b*BP + p  (2048 blocks); loop over all 32 h rows inside.
    int blk = blockIdx.x;
    int p = blk & 63;
    int b = blk >> 6;
    int i = p >> 3;
    int j = p & 7;

    __shared__ float s_sx, s_sy, s_tx, s_ty;
    if (threadIdx.x == 0) {
        float sx, sy, tx, ty;
        compute_params(zw, b, i, j, sx, sy, tx, ty);
        s_sx = sx; s_sy = sy; s_tx = tx; s_ty = ty;

        // fold the bbox-mask output into this kernel
        float bh  = sy * 0.5f;
        float bw  = sx * 0.5f;
        float bty = (ty + 1.0f) * 0.5f;
        float btx = (tx + 1.0f) * 0.5f;
        float4 m;
        m.x = bty - bh;
        m.y = btx - bw;
        m.z = bty + bh;
        m.w = btx + bw;
        __stcs((float4*)mask + blk, m);
    }
    __syncthreads();

    int tid = threadIdx.x;      // 256 threads
    int c4  = tid & 7;          // channel quad 0..7 (4 floats each)
    int w   = tid >> 3;         // 0..31

    // ---- x-side: loop-invariant across h ----
    float xs = -1.0f + 2.0f * (float)w / 31.0f;
    float gx = s_sx * xs + s_tx;
    float px = 0.5f * (gx + 1.0f) * (float)(WX - 1);
    float x0 = floorf(px), x1 = x0 + 1.0f;
    x0 = fminf(fmaxf(x0, 0.0f), (float)(WX - 1));
    x1 = fminf(fmaxf(x1, 0.0f), (float)(WX - 1));
    float wx0 = x1 - px;        // weight for x0 column
    float wx1 = px - x0;        // weight for x1 column
    int col0 = (int)x0 * (CH / 4) + c4;
    int col1 = (int)x1 * (CH / 4) + c4;

    const float4* __restrict__ img =
        (const float4*)(x + (size_t)b * HX * WX * CH);
    float4* __restrict__ op =
        (float4*)out + (size_t)blk * (H_OUT * W_OUT * (CH / 4));

    float sy_ = s_sy, ty_ = s_ty;

    // Rolling corner registers. Rows are BLOCK-UNIFORM (depend only on h and
    // shared params) and monotone nondecreasing in h, so the reuse branch is
    // divergence-free. A = upper row (row0), B = lower row (row1).
    float4 A0, A1, B0, B1;
    int rowB = -1;              // image row currently held in B0/B1

#pragma unroll 4
    for (int h = 0; h < H_OUT; h++) {
        float ys = -1.0f + 2.0f * (float)h / 31.0f;
        float gy = sy_ * ys + ty_;
        float py = 0.5f * (gy + 1.0f) * (float)(HX - 1);
        float y0 = floorf(py), y1 = y0 + 1.0f;
        y0 = fminf(fmaxf(y0, 0.0f), (float)(HX - 1));
        y1 = fminf(fmaxf(y1, 0.0f), (float)(HX - 1));
        float wy0 = y1 - py;
        float wy1 = py - y0;

        int r0 = (int)y0;
        int r1 = (int)y1;

        if (r0 == rowB) {
            // common case (py step ~1): upper row == previous lower row
            A0 = B0; A1 = B1;
        } else {
            int base = r0 * (WX * (CH / 4));
            A0 = img[base + col0];
            A1 = img[base + col1];
        }
        {
            // always load the lower row (r1==r0 clip case is an L1 hit)
            int base = r1 * (WX * (CH / 4));
            B0 = img[base + col0];
            B1 = img[base + col1];
        }
        rowB = r1;

        float wa = wx0 * wy0;
        float wb = wx0 * wy1;
        float wc = wx1 * wy0;
        float wd = wx1 * wy1;

        float4 o;
        o.x = wa * A0.x + wb * B0.x + wc * A1.x + wd * B1.x;
        o.y = wa * A0.y + wb * B0.y + wc * A1.y + wd * B1.y;
        o.z = wa * A0.z + wb * B0.z + wc * A1.z + wd * B1.z;
        o.w = wa * A0.w + wb * B0.w + wc * A1.w + wd * B1.w;

        // w*8 + c4 == tid -> fully coalesced; streaming store (never re-read)
        __stcs(&op[h * (W_OUT * (CH / 4)) + tid], o);
    }
}

extern "C" void kernel_launch(void* const* d_in, const int* in_sizes, int n_in,
                              void* d_out, int out_size)
{
    const float* x  = (const float*)d_in[0];
    const float* zw = (const float*)d_in[1];
    float* out = (float*)d_out;

    stn_sample_kernel<<<BB * BP, 256>>>(x, zw, out, out + OUT_ELEMS);
}

// round 11
// speedup vs baseline: 1.0567x; 1.0567x over previous
#include <cuda_runtime.h>
#include <math.h>

#define H_OUT 32
#define W_OUT 32
#define HX 128
#define WX 128
#define CH 32
#define BB 32
#define BP 64           // 8*8 objects
#define ROWS_PER_BLK 8  // h-quarter per block
#define NBLK (BB * BP * (H_OUT / ROWS_PER_BLK))   // 8192

// out elements = B*BP*H_OUT*W_OUT*CH
#define OUT_ELEMS (32ll*64*32*32*32)

__global__ void __launch_bounds__(256, 4)
stn_sample_kernel(const float* __restrict__ x,
                  const float* __restrict__ zw,
                  float* __restrict__ out,
                  float* __restrict__ mask)
{
    // blk = obj*4 + q ; obj = b*64 + p ; q selects 8 of 32 h rows
    int blk = blockIdx.x;
    int q   = blk & 3;
    int obj = blk >> 2;
    int p   = obj & 63;
    int b   = obj >> 6;
    int i   = p >> 3;
    int j   = p & 7;

    // ---- per-thread params (broadcast loads, no smem / no syncthreads) ----
    // zw layout [B,8,8,4] contiguous
    const float* zp = zw + (size_t)obj * 4;
    float z0 = __ldg(zp + 0);
    float z1 = __ldg(zp + 1);
    float z2 = __ldg(zp + 2);
    float z3 = __ldg(zp + 3);
    float sx = 0.5f / (1.0f + expf(-z0));
    float sy = 0.5f / (1.0f + expf(-z1));
    float bias_tx = 1.5f * (float)j / 7.0f - 0.75f;
    float bias_ty = 1.5f * (float)i / 7.0f - 0.75f;
    float tx = 0.5f * tanhf(z2) + bias_tx;
    float ty = 0.5f * tanhf(z3) + bias_ty;

    if (q == 0 && threadIdx.x == 0) {
        float bh  = sy * 0.5f;
        float bw  = sx * 0.5f;
        float bty = (ty + 1.0f) * 0.5f;
        float btx = (tx + 1.0f) * 0.5f;
        float* mp = mask + (size_t)obj * 4;
        mp[0] = bty - bh;
        mp[1] = btx - bw;
        mp[2] = bty + bh;
        mp[3] = btx + bw;
    }

    int tid = threadIdx.x;      // 256 threads
    int c4  = tid & 7;          // channel quad 0..7 (4 floats each)
    int w   = tid >> 3;         // 0..31

    // ---- x-side: invariant across h ----
    float xs = -1.0f + 2.0f * (float)w / 31.0f;
    float gx = sx * xs + tx;
    float px = 0.5f * (gx + 1.0f) * (float)(WX - 1);
    float x0 = floorf(px), x1 = x0 + 1.0f;
    x0 = fminf(fmaxf(x0, 0.0f), (float)(WX - 1));
    x1 = fminf(fmaxf(x1, 0.0f), (float)(WX - 1));
    float wx0 = x1 - px;
    float wx1 = px - x0;
    int col0 = (int)x0 * (CH / 4) + c4;
    int col1 = (int)x1 * (CH / 4) + c4;

    const float4* __restrict__ img =
        (const float4*)(x + (size_t)b * HX * WX * CH);
    float4* __restrict__ op =
        (float4*)out + (size_t)obj * (H_OUT * W_OUT * (CH / 4))
                     + (size_t)q * (ROWS_PER_BLK * W_OUT * (CH / 4));

#pragma unroll
    for (int hh = 0; hh < ROWS_PER_BLK; hh++) {
        int h = q * ROWS_PER_BLK + hh;
        float ys = -1.0f + 2.0f * (float)h / 31.0f;
        float gy = sy * ys + ty;
        float py = 0.5f * (gy + 1.0f) * (float)(HX - 1);
        float y0 = floorf(py), y1 = y0 + 1.0f;
        y0 = fminf(fmaxf(y0, 0.0f), (float)(HX - 1));
        y1 = fminf(fmaxf(y1, 0.0f), (float)(HX - 1));
        float wy0 = y1 - py;
        float wy1 = py - y0;

        int row0 = (int)y0 * (WX * (CH / 4));
        int row1 = (int)y1 * (WX * (CH / 4));

        float4 Ia = img[row0 + col0];
        float4 Ib = img[row1 + col0];
        float4 Ic = img[row0 + col1];
        float4 Id = img[row1 + col1];

        float wa = wx0 * wy0;
        float wb = wx0 * wy1;
        float wc = wx1 * wy0;
        float wd = wx1 * wy1;

        float4 o;
        o.x = wa * Ia.x + wb * Ib.x + wc * Ic.x + wd * Id.x;
        o.y = wa * Ia.y + wb * Ib.y + wc * Ic.y + wd * Id.y;
        o.z = wa * Ia.z + wb * Ib.z + wc * Ic.z + wd * Id.z;
        o.w = wa * Ia.w + wb * Ib.w + wc * Ic.w + wd * Id.w;

        // w*8 + c4 == tid -> fully coalesced; streaming store (never re-read)
        __stcs(&op[hh * (W_OUT * (CH / 4)) + tid], o);
    }
}

extern "C" void kernel_launch(void* const* d_in, const int* in_sizes, int n_in,
                              void* d_out, int out_size)
{
    const float* x  = (const float*)d_in[0];
    const float* zw = (const float*)d_in[1];
    float* out = (float*)d_out;

    stn_sample_kernel<<<NBLK, 256>>>(x, zw, out, out + OUT_ELEMS);
}